// round 17
// baseline (speedup 1.0000x reference)
#include <cuda_runtime.h>
#include <cstdint>

// ============================================================================
// AmbientSphericalBrownianMotion — Stratonovich-Heun BM on S^2, N=4.2M pts,
// 100 steps. Bit-exact JAX threefry2x32 random bits (partitionable:
// bits0 ^ bits1). Issue-bound: threefry adds on IMAD (fma pipe) via opaque
// multiplier, SHF+LOP on alu pipe; projective Heun step (no rcp); lg2-domain
// erfinv with the |u|->1 clamp moved into the rare tail block (central path
// clamp-free); key prefetch + unroll-2.
// ============================================================================

#define MAX_STEPS 4096
struct __align__(16) StepKey {
    uint4 a;   // k0, k1, k2, k2+1
    uint4 b;   // k0+2, k1+3, k2+4, k0+5
};
__device__ StepKey g_step_keys[MAX_STEPS + 1];   // +1: unguarded s+1 prefetch

__device__ __forceinline__ uint32_t rotl32(uint32_t v, int r) {
    return __funnelshift_l(v, v, r);
}

// add via IMAD (fma pipe): d = a*one + c, with `one` runtime-opaque == 1.
__device__ __forceinline__ uint32_t imad1(uint32_t a, uint32_t one, uint32_t c) {
    uint32_t d;
    asm("mad.lo.u32 %0, %1, %2, %3;" : "=r"(d) : "r"(a), "r"(one), "r"(c));
    return d;
}

// threefry round: add on fma pipe (IMAD); rot+xor on alu pipe (SHF+LOP)
__device__ __forceinline__ void tfr(uint32_t& x0, uint32_t& x1, int r, uint32_t one) {
    x0 = imad1(x0, one, x1);
    x1 = rotl32(x1, r) ^ x0;
}

// JAX partitionable random_bits(32): bits0 ^ bits1, sign-flip folded into the
// final 3-input LOP3. All adds as IMAD: alu pipe sees 2 ops/round + 1 LOP3.
__device__ __forceinline__ int32_t tf_sbits(const StepKey& k, uint32_t x1init,
                                            uint32_t one) {
    uint32_t x0 = k.a.x;   // c0 = 0, so x0 = k0
    uint32_t x1 = x1init;  // c1 + k1, pre-added by caller
    tfr(x0, x1, 13, one); tfr(x0, x1, 15, one);
    tfr(x0, x1, 26, one); tfr(x0, x1, 6,  one);
    x0 = imad1(x0, one, k.a.y);  x1 = imad1(x1, one, k.a.w);  // +k1, +(k2+1)
    tfr(x0, x1, 17, one); tfr(x0, x1, 29, one);
    tfr(x0, x1, 16, one); tfr(x0, x1, 24, one);
    x0 = imad1(x0, one, k.a.z);  x1 = imad1(x1, one, k.b.x);  // +k2, +(k0+2)
    tfr(x0, x1, 13, one); tfr(x0, x1, 15, one);
    tfr(x0, x1, 26, one); tfr(x0, x1, 6,  one);
    x0 = imad1(x0, one, k.a.x);  x1 = imad1(x1, one, k.b.y);  // +k0, +(k1+3)
    tfr(x0, x1, 17, one); tfr(x0, x1, 29, one);
    tfr(x0, x1, 16, one); tfr(x0, x1, 24, one);
    x0 = imad1(x0, one, k.a.y);  x1 = imad1(x1, one, k.b.z);  // +k1, +(k2+4)
    tfr(x0, x1, 13, one); tfr(x0, x1, 15, one);
    tfr(x0, x1, 26, one); tfr(x0, x1, 6,  one);
    uint32_t o0 = imad1(x0, one, k.a.z);   // +k2
    uint32_t o1 = imad1(x1, one, k.b.w);   // +(k0+5)
    return (int32_t)(o0 ^ o1 ^ 0x80000000u);
}

// ---- fast-math primitives ----
__device__ __forceinline__ float lg2_fast(float x) {
    float r; asm("lg2.approx.f32 %0, %1;" : "=f"(r) : "f"(x)); return r;
}
__device__ __forceinline__ float rsqrt_fast(float x) {
    float r; asm("rsqrt.approx.f32 %0, %1;" : "=f"(r) : "f"(x)); return r;
}
__device__ __forceinline__ float sqrt_fast(float x) {
    float r; asm("sqrt.approx.f32 %0, %1;" : "=f"(r) : "f"(x)); return r;
}

// signed bits -> uniform(-1,1) -> sqrt2*erfinv(u)*sqrt_dt  (scale = sqrt2*sqrt_dt)
// lg2 domain throughout. Central path is clamp-free: the |u|->1 guard only
// binds for L < -23, which lies strictly inside the tail region (L <= -7.21),
// and tail lanes overwrite p via SEL. The clamp lives inside the rare
// warp-uniform tail block as an fminf on m.
__device__ __forceinline__ float normal_from_sbits(int32_t sb, float scale) {
    float u  = __int2float_rn(sb) * 4.6566128730773926e-10f;   // 2^-31
    float us = u * scale;
    float L  = lg2_fast(fmaf(-u, u, 1.0f));                    // log2(1-u^2), may be -inf
    float w  = fmaf(L, -0.69314718f, -2.5f);                   // w_central
    float p;
    p =            2.81022636e-08f;
    p = fmaf(p, w, 3.43273939e-07f);
    p = fmaf(p, w, -3.5233877e-06f);
    p = fmaf(p, w, -4.39150654e-06f);
    p = fmaf(p, w, 0.00021858087f);
    p = fmaf(p, w, -0.00125372503f);
    p = fmaf(p, w, -0.00417768164f);
    p = fmaf(p, w, 0.246640727f);
    p = fmaf(p, w, 1.50140941f);
    bool tail = !(L > -7.2134752f);            // m >= 5 (catches -inf too)
    if (__any_sync(0xffffffffu, tail)) {
        float m  = fminf(L * -0.69314718f, 15.9468f);   // clamp |u|->1 corner here
        float wt = sqrt_fast(m) - 3.0f;
        float pt;
        pt =             -0.000200214257f;
        pt = fmaf(pt, wt, 0.000100950558f);
        pt = fmaf(pt, wt, 0.00134934322f);
        pt = fmaf(pt, wt, -0.00367342844f);
        pt = fmaf(pt, wt, 0.00573950773f);
        pt = fmaf(pt, wt, -0.0076224613f);
        pt = fmaf(pt, wt, 0.00943887047f);
        pt = fmaf(pt, wt, 1.00167406f);
        pt = fmaf(pt, wt, 2.83297682f);
        p = tail ? pt : p;
    }
    return p * us;
}

__device__ __forceinline__ float dot3(float a0, float a1, float a2,
                                      float b0, float b1, float b2) {
    return fmaf(a2, b2, fmaf(a1, b1, a0 * b0));
}

// ---------------------------------------------------------------------------
// Pre-kernel: per-step folded keys + precomputed injection constants.
//   fold_in(key(1), s) = threefry((0,1),(0,s))
// ---------------------------------------------------------------------------
__device__ __forceinline__ void tfr_p(uint32_t& x0, uint32_t& x1, int r) {
    x0 += x1; x1 = rotl32(x1, r) ^ x0;
}
__global__ void keys_kernel(const int* __restrict__ steps_ptr) {
    int steps = *steps_ptr;
    if (steps > MAX_STEPS) steps = MAX_STEPS;
    // fill [0, steps] inclusive: entry [steps] is a valid dummy so the main
    // loop's s+1 prefetch never reads uninitialized/out-of-bounds memory
    for (int s = threadIdx.x; s <= steps; s += blockDim.x) {
        const uint32_t k0 = 0u, k1 = 1u;
        const uint32_t k2 = k0 ^ k1 ^ 0x1BD11BDAu;
        uint32_t x0 = k0, x1 = (uint32_t)s + k1;
        tfr_p(x0,x1,13); tfr_p(x0,x1,15); tfr_p(x0,x1,26); tfr_p(x0,x1,6);
        x0 += k1; x1 += k2 + 1u;
        tfr_p(x0,x1,17); tfr_p(x0,x1,29); tfr_p(x0,x1,16); tfr_p(x0,x1,24);
        x0 += k2; x1 += k0 + 2u;
        tfr_p(x0,x1,13); tfr_p(x0,x1,15); tfr_p(x0,x1,26); tfr_p(x0,x1,6);
        x0 += k0; x1 += k1 + 3u;
        tfr_p(x0,x1,17); tfr_p(x0,x1,29); tfr_p(x0,x1,16); tfr_p(x0,x1,24);
        x0 += k1; x1 += k2 + 4u;
        tfr_p(x0,x1,13); tfr_p(x0,x1,15); tfr_p(x0,x1,26); tfr_p(x0,x1,6);
        uint32_t fk0 = x0 + k2;
        uint32_t fk1 = x1 + k0 + 5u;
        uint32_t fk2 = fk0 ^ fk1 ^ 0x1BD11BDAu;
        StepKey sk;
        sk.a = make_uint4(fk0, fk1, fk2, fk2 + 1u);
        sk.b = make_uint4(fk0 + 2u, fk1 + 3u, fk2 + 4u, fk0 + 5u);
        g_step_keys[s] = sk;
    }
}

// ---------------------------------------------------------------------------
// Main kernel: one thread per point, full trajectory in registers.
// Projective Heun step: z rescaled by D = 1+q' (absorbed by normalization):
//   s  = 1 + q/2 ;  a' = s - a ;  b' = s - a/2 - a^2/2
//   z  = a'*x + b'*v ;  x_new = z * rsqrt(z.z)
// ---------------------------------------------------------------------------
__global__ void __launch_bounds__(256)
sbm_kernel(const float* __restrict__ xin,
           const int* __restrict__ t_ptr,
           const int* __restrict__ steps_ptr,
           float* __restrict__ out, int n) {
    int i = blockIdx.x * blockDim.x + threadIdx.x;
    if (i >= n) return;

    const int steps = *steps_ptr;
    const float dt = (float)(*t_ptr) / (float)steps;
    const float scale = 1.4142135381698608f * sqrtf(dt);   // sqrt2 * sqrt_dt
    const uint32_t one = umin((uint32_t)steps, 1u);        // opaque 1 for IMAD

    float x0 = xin[3 * i + 0];
    float x1 = xin[3 * i + 1];
    float x2 = xin[3 * i + 2];

    const uint32_t base = 3u * (uint32_t)i;

    StepKey k = g_step_keys[0];

    #pragma unroll 2
    for (int s = 0; s < steps; ++s) {
        const StepKey kn = g_step_keys[s + 1];   // prefetch next step's key

        // three fresh signed random words for this (point, step);
        // counters computed in parallel (no serial IMAD ladder)
        const uint32_t c1k = base + k.a.y;   // counter + k1, shared init
        int32_t b0 = tf_sbits(k, c1k,      one);
        int32_t b1 = tf_sbits(k, c1k + 1u, one);
        int32_t b2 = tf_sbits(k, c1k + 2u, one);

        float v0 = normal_from_sbits(b0, scale);
        float v1 = normal_from_sbits(b1, scale);
        float v2 = normal_from_sbits(b2, scale);

        // projective Heun step (no division)
        float a  = dot3(x0, x1, x2, v0, v1, v2);
        float q  = dot3(v0, v1, v2, v0, v1, v2);
        float sc = fmaf(0.5f, q, 1.0f);          // 1 + q/2
        float al = sc - a;                       // D*alpha
        float h  = 0.5f * a;
        float be = fmaf(-h, a, sc - h);          // D*beta

        float z0 = fmaf(be, v0, al * x0);
        float z1 = fmaf(be, v1, al * x1);
        float z2 = fmaf(be, v2, al * x2);

        float inv = rsqrt_fast(dot3(z0, z1, z2, z0, z1, z2));
        x0 = z0 * inv;
        x1 = z1 * inv;
        x2 = z2 * inv;

        k = kn;
    }

    out[3 * i + 0] = x0;
    out[3 * i + 1] = x1;
    out[3 * i + 2] = x2;
}

// ---------------------------------------------------------------------------
extern "C" void kernel_launch(void* const* d_in, const int* in_sizes, int n_in,
                              void* d_out, int out_size) {
    const float* x     = (const float*)d_in[0];
    const int*   t     = (const int*)d_in[1];
    const int*   steps = (const int*)d_in[2];
    const int n = in_sizes[0] / 3;

    keys_kernel<<<1, 256>>>(steps);

    const int threads = 256;
    const int blocks = (n + threads - 1) / threads;
    sbm_kernel<<<blocks, threads>>>(x, t, steps, (float*)d_out, n);
}